// round 17
// baseline (speedup 1.0000x reference)
#include <cuda_runtime.h>
#include <math.h>

#define NB 64
#define NT 128
#define NN 64
#define NC 128
#define NH 64
#define NE 192
#define TP 68
#define WP 104   // phase2 sWh pitch (u32)
#define GP 104   // phase2 sG pitch
#define HP 196   // phase2 Hcat pitch
#define PB 68    // phase1 buffer pitch

// U[b,t,n,e] fp32 (biases included). 384 MiB.
static __device__ float g_U[(size_t)NB * NT * NN * NE];
// Pooled hidden means per (b,t). 2 MiB.
static __device__ float g_pool[(size_t)NB * NT * NH];
// tf32 lo-part of hidden-path weights, [k=192][e=192]. 147 KB (L2-resident).
static __device__ unsigned g_Wl[192 * 192];
// tf32 hi/lo of input-path weights [k=192][e=192], and encoder [k=128][d=64].
static __device__ unsigned g_Wuh[192 * 192];
static __device__ unsigned g_Wul[192 * 192];
static __device__ unsigned g_eWh[128 * 64];
static __device__ unsigned g_eWl[128 * 64];

__device__ __forceinline__ unsigned smem_u32(const void* p) {
    unsigned r;
    asm("{ .reg .u64 t; cvta.to.shared.u64 t, %1; cvt.u32.u64 %0, t; }" : "=r"(r) : "l"(p));
    return r;
}
__device__ __forceinline__ unsigned cluster_rank() {
    unsigned r; asm("mov.u32 %0, %%cluster_ctarank;" : "=r"(r)); return r;
}
__device__ __forceinline__ void st_peer_f2(unsigned laddr, unsigned peer, float a, float b) {
    unsigned raddr;
    asm volatile("mapa.shared::cluster.u32 %0, %1, %2;" : "=r"(raddr) : "r"(laddr), "r"(peer));
    asm volatile("st.shared::cluster.v2.f32 [%0], {%1, %2};" :: "r"(raddr), "f"(a), "f"(b) : "memory");
}
#define CLUSTER_ARRIVE() asm volatile("barrier.cluster.arrive.aligned;" ::: "memory")
#define CLUSTER_WAIT()   asm volatile("barrier.cluster.wait.aligned;" ::: "memory")
#define CLUSTER_SYNC() do { CLUSTER_ARRIVE(); CLUSTER_WAIT(); } while (0)

__device__ __forceinline__ float rcp_ap(float x) {
    float y; asm("rcp.approx.f32 %0, %1;" : "=f"(y) : "f"(x)); return y;
}
__device__ __forceinline__ float tanh_fast(float x) {
    return 1.0f - 2.0f * rcp_ap(1.0f + __expf(2.0f * x));
}
__device__ __forceinline__ float sig_fast(float x) {
    return rcp_ap(1.0f + __expf(-x));
}
__device__ __forceinline__ unsigned f2tf(float x) {
    unsigned u; asm("cvt.rna.tf32.f32 %0, %1;" : "=r"(u) : "f"(x)); return u;
}
__device__ __forceinline__ void mma_tf32(float c[4], const unsigned a[4],
                                         unsigned b0, unsigned b1) {
    asm volatile(
        "mma.sync.aligned.m16n8k8.row.col.f32.tf32.tf32.f32 "
        "{%0,%1,%2,%3}, {%4,%5,%6,%7}, {%8,%9}, {%0,%1,%2,%3};"
        : "+f"(c[0]), "+f"(c[1]), "+f"(c[2]), "+f"(c[3])
        : "r"(a[0]), "r"(a[1]), "r"(a[2]), "r"(a[3]), "r"(b0), "r"(b1));
}

// ---------------------------------------------------------------------------
// prep2: tf32 lo-part of hidden weights, layout [k][e].
// ---------------------------------------------------------------------------
__global__ void prep2_kernel(const float* __restrict__ Wfh, const float* __restrict__ Wgh,
                             const float* __restrict__ Wch) {
    int i = blockIdx.x * 256 + threadIdx.x;
    if (i >= 36864) return;
    int k = i / 192, e = i % 192;
    int hop = k >> 6, dm = k & 63;
    int gate = e >> 6, dc = e & 63;
    const float* W = (gate == 0) ? Wfh : ((gate == 1) ? Wgh : Wch);
    float w = W[hop * 4096 + dm * 64 + dc];
    unsigned hi = f2tf(w);
    g_Wl[i] = f2tf(w - __uint_as_float(hi));
}

// prep1: tf32 hi/lo of input-path weights + encoder weights.
__global__ void prep1_kernel(const float* __restrict__ Wfu, const float* __restrict__ Wgu,
                             const float* __restrict__ Wcu, const float* __restrict__ encW) {
    int i = blockIdx.x * 256 + threadIdx.x;
    if (i < 36864) {
        int k = i / 192, e = i % 192;
        int hop = k >> 6, dm = k & 63;
        int gate = e >> 6, dc = e & 63;
        const float* W = (gate == 0) ? Wfu : ((gate == 1) ? Wgu : Wcu);
        float w = W[hop * 4096 + dm * 64 + dc];
        unsigned hi = f2tf(w);
        g_Wuh[i] = hi;
        g_Wul[i] = f2tf(w - __uint_as_float(hi));
    } else {
        int j = i - 36864;
        if (j < 8192) {
            float w = encW[j];
            unsigned hi = f2tf(w);
            g_eWh[j] = hi;
            g_eWl[j] = f2tf(w - __uint_as_float(hi));
        }
    }
}

// ---------------------------------------------------------------------------
// Phase 1: ALL tensor, B-side from prepped tf32 tables.
// grid 8192, block 256, 2 CTAs/SM. smem = 69632 B.
// ---------------------------------------------------------------------------
__device__ __forceinline__ void mm_mma(float* __restrict__ dst,
                                       const float* __restrict__ sAN,
                                       const float* __restrict__ src,
                                       int g, int t4, int col0)
{
    float cm[4][4];
#pragma unroll
    for (int mt = 0; mt < 4; mt++)
#pragma unroll
        for (int q = 0; q < 4; q++) cm[mt][q] = 0.f;

#pragma unroll 1
    for (int kc = 0; kc < 8; kc++) {
        int k0 = kc * 8;
        float x0 = src[(k0 + t4) * PB + col0 + g];
        float x1 = src[(k0 + t4 + 4) * PB + col0 + g];
        unsigned bh0 = f2tf(x0), bh1 = f2tf(x1);
        unsigned bl0 = f2tf(x0 - __uint_as_float(bh0));
        unsigned bl1 = f2tf(x1 - __uint_as_float(bh1));
#pragma unroll
        for (int mt = 0; mt < 4; mt++) {
            int r0 = mt * 16 + g;
            float a0f = sAN[r0 * PB + k0 + t4];
            float a1f = sAN[(r0 + 8) * PB + k0 + t4];
            float a2f = sAN[r0 * PB + k0 + t4 + 4];
            float a3f = sAN[(r0 + 8) * PB + k0 + t4 + 4];
            unsigned ah[4] = {f2tf(a0f), f2tf(a1f), f2tf(a2f), f2tf(a3f)};
            unsigned al[4] = {f2tf(a0f - __uint_as_float(ah[0])),
                              f2tf(a1f - __uint_as_float(ah[1])),
                              f2tf(a2f - __uint_as_float(ah[2])),
                              f2tf(a3f - __uint_as_float(ah[3]))};
            mma_tf32(cm[mt], ah, bh0, bh1);
            mma_tf32(cm[mt], al, bh0, bh1);
            mma_tf32(cm[mt], ah, bl0, bl1);
        }
    }
#pragma unroll
    for (int mt = 0; mt < 4; mt++) {
        int r0 = mt * 16 + g;
        *(float2*)&dst[r0 * PB + col0 + 2 * t4] = make_float2(cm[mt][0], cm[mt][1]);
        *(float2*)&dst[(r0 + 8) * PB + col0 + 2 * t4] = make_float2(cm[mt][2], cm[mt][3]);
    }
}

__global__ void __launch_bounds__(256, 2) phase1_kernel(
    const float* __restrict__ frames, const float* __restrict__ adj,
    const float* __restrict__ encB,
    const float* __restrict__ bf, const float* __restrict__ bg, const float* __restrict__ bc)
{
    extern __shared__ float sm[];
    float* sAN = sm;               // 4352
    float* sX  = sm + 4352;
    float* sY1 = sm + 8704;
    float* sY2 = sm + 13056;

    const int tid = threadIdx.x;
    const int bt = blockIdx.x;
    const float* fr = frames + (size_t)bt * (NC * NN);
    const float* Ap = adj + (size_t)bt * (NN * NN);

    for (int i = tid; i < NN * NN; i += 256) {
        int n = i >> 6, m = i & 63;
        sAN[n * PB + m] = Ap[i];
    }

    const int w = tid >> 5;
    const int lane = tid & 31;
    const int g = lane >> 2;
    const int t4 = lane & 3;
    const int col0 = w * 8;

    // encode: x = fr^T @ encW + encB (B hi/lo from tables)
    {
        float ce[4][4];
        {
            float b0v = __ldg(&encB[col0 + 2 * t4]);
            float b1v = __ldg(&encB[col0 + 2 * t4 + 1]);
#pragma unroll
            for (int mt = 0; mt < 4; mt++) {
                ce[mt][0] = b0v; ce[mt][1] = b1v;
                ce[mt][2] = b0v; ce[mt][3] = b1v;
            }
        }
#pragma unroll 1
        for (int kc = 0; kc < 16; kc++) {
            int k0 = kc * 8;
            unsigned bh0 = __ldg(&g_eWh[(k0 + t4) * 64 + col0 + g]);
            unsigned bh1 = __ldg(&g_eWh[(k0 + t4 + 4) * 64 + col0 + g]);
            unsigned bl0 = __ldg(&g_eWl[(k0 + t4) * 64 + col0 + g]);
            unsigned bl1 = __ldg(&g_eWl[(k0 + t4 + 4) * 64 + col0 + g]);
#pragma unroll
            for (int mt = 0; mt < 4; mt++) {
                int r0 = mt * 16 + g;
                float a0f = __ldg(&fr[(k0 + t4) * 64 + r0]);
                float a1f = __ldg(&fr[(k0 + t4) * 64 + r0 + 8]);
                float a2f = __ldg(&fr[(k0 + t4 + 4) * 64 + r0]);
                float a3f = __ldg(&fr[(k0 + t4 + 4) * 64 + r0 + 8]);
                unsigned ah[4] = {f2tf(a0f), f2tf(a1f), f2tf(a2f), f2tf(a3f)};
                unsigned al[4] = {f2tf(a0f - __uint_as_float(ah[0])),
                                  f2tf(a1f - __uint_as_float(ah[1])),
                                  f2tf(a2f - __uint_as_float(ah[2])),
                                  f2tf(a3f - __uint_as_float(ah[3]))};
                mma_tf32(ce[mt], ah, bh0, bh1);
                mma_tf32(ce[mt], al, bh0, bh1);
                mma_tf32(ce[mt], ah, bl0, bl1);
            }
        }
#pragma unroll
        for (int mt = 0; mt < 4; mt++) {
            int r0 = mt * 16 + g;
            *(float2*)&sX[r0 * PB + col0 + 2 * t4] = make_float2(ce[mt][0], ce[mt][1]);
            *(float2*)&sX[(r0 + 8) * PB + col0 + 2 * t4] = make_float2(ce[mt][2], ce[mt][3]);
        }
    }
    __syncthreads();

    mm_mma(sY1, sAN, sX, g, t4, col0);
    __syncthreads();
    mm_mma(sY2, sAN, sY1, g, t4, col0);
    __syncthreads();

    // gate GEMM: B hi/lo from g_Wuh/g_Wul tables
    const int e0 = w * 24;
    const float* Bp[3];
#pragma unroll
    for (int nt = 0; nt < 3; nt++) {
        int e = e0 + nt * 8;
        int gate = e >> 6;
        Bp[nt] = (gate == 0) ? bf : ((gate == 1) ? bg : bc);
    }

    float cacc[4][3][4];
#pragma unroll
    for (int nt = 0; nt < 3; nt++) {
        int dcn = (e0 + nt * 8) & 63;
        float b0v = __ldg(Bp[nt] + dcn + 2 * t4);
        float b1v = __ldg(Bp[nt] + dcn + 2 * t4 + 1);
#pragma unroll
        for (int mt = 0; mt < 4; mt++) {
            cacc[mt][nt][0] = b0v; cacc[mt][nt][1] = b1v;
            cacc[mt][nt][2] = b0v; cacc[mt][nt][3] = b1v;
        }
    }

    const float* bufs[3] = {sX, sY1, sY2};
#pragma unroll 1
    for (int kt = 0; kt < 24; kt++) {
        const int hop = kt >> 3;
        const int dk0 = (kt & 7) * 8;
        const float* Bf = bufs[hop];
        const int krow = hop * 64 + dk0 + t4;

        float afv[4][4];
        unsigned ah[4][4];
#pragma unroll
        for (int mt = 0; mt < 4; mt++) {
            int r0 = (mt * 16 + g) * PB;
            int r1 = r0 + 8 * PB;
            afv[mt][0] = Bf[r0 + dk0 + t4];
            afv[mt][1] = Bf[r1 + dk0 + t4];
            afv[mt][2] = Bf[r0 + dk0 + t4 + 4];
            afv[mt][3] = Bf[r1 + dk0 + t4 + 4];
#pragma unroll
            for (int q = 0; q < 4; q++) ah[mt][q] = f2tf(afv[mt][q]);
        }

        unsigned bh[3][2];
#pragma unroll
        for (int nt = 0; nt < 3; nt++) {
            int ecol = e0 + nt * 8 + g;
            bh[nt][0] = __ldg(&g_Wuh[krow * 192 + ecol]);
            bh[nt][1] = __ldg(&g_Wuh[(krow + 4) * 192 + ecol]);
            unsigned bl0 = __ldg(&g_Wul[krow * 192 + ecol]);
            unsigned bl1 = __ldg(&g_Wul[(krow + 4) * 192 + ecol]);
#pragma unroll
            for (int mt = 0; mt < 4; mt++) {
                mma_tf32(cacc[mt][nt], ah[mt], bh[nt][0], bh[nt][1]);
                mma_tf32(cacc[mt][nt], ah[mt], bl0, bl1);
            }
        }

        unsigned al[4][4];
#pragma unroll
        for (int mt = 0; mt < 4; mt++)
#pragma unroll
            for (int q = 0; q < 4; q++)
                al[mt][q] = f2tf(afv[mt][q] - __uint_as_float(ah[mt][q]));
#pragma unroll
        for (int nt = 0; nt < 3; nt++)
#pragma unroll
            for (int mt = 0; mt < 4; mt++)
                mma_tf32(cacc[mt][nt], al[mt], bh[nt][0], bh[nt][1]);
    }

    float* Ub = g_U + (size_t)bt * (NN * NE);
#pragma unroll
    for (int mt = 0; mt < 4; mt++) {
        int row = mt * 16 + g;
#pragma unroll
        for (int nt = 0; nt < 3; nt++) {
            int col = e0 + nt * 8 + 2 * t4;
            *(float2*)&Ub[row * NE + col] = make_float2(cacc[mt][nt][0], cacc[mt][nt][1]);
            *(float2*)&Ub[(row + 8) * NE + col] = make_float2(cacc[mt][nt][2], cacc[mt][nt][3]);
        }
    }
}

// ---------------------------------------------------------------------------
// Phase 2: e/d-split cluster recurrence, one exchange per step,
// fused mm+gate segments for ILP. grid 128, block 512. smem = 174080 B.
// ---------------------------------------------------------------------------
__device__ __forceinline__ void mm_mma2(float* __restrict__ dst,
                                        const float* __restrict__ sAN,
                                        const float* __restrict__ src,
                                        int g, int t4, int colm, int mt2)
{
    float cm[2][4];
#pragma unroll
    for (int i = 0; i < 2; i++)
#pragma unroll
        for (int q = 0; q < 4; q++) cm[i][q] = 0.f;

#pragma unroll 1
    for (int kc = 0; kc < 8; kc++) {
        int k0 = kc * 8;
        float x0 = src[(k0 + t4) * HP + colm + g];
        float x1 = src[(k0 + t4 + 4) * HP + colm + g];
        unsigned bh0 = f2tf(x0), bh1 = f2tf(x1);
        unsigned bl0 = f2tf(x0 - __uint_as_float(bh0));
        unsigned bl1 = f2tf(x1 - __uint_as_float(bh1));
#pragma unroll
        for (int i = 0; i < 2; i++) {
            int r0 = (mt2 + i) * 16 + g;
            float a0f = sAN[r0 * TP + k0 + t4];
            float a1f = sAN[(r0 + 8) * TP + k0 + t4];
            float a2f = sAN[r0 * TP + k0 + t4 + 4];
            float a3f = sAN[(r0 + 8) * TP + k0 + t4 + 4];
            unsigned ah[4] = {f2tf(a0f), f2tf(a1f), f2tf(a2f), f2tf(a3f)};
            unsigned al[4] = {f2tf(a0f - __uint_as_float(ah[0])),
                              f2tf(a1f - __uint_as_float(ah[1])),
                              f2tf(a2f - __uint_as_float(ah[2])),
                              f2tf(a3f - __uint_as_float(ah[3]))};
            mma_tf32(cm[i], ah, bh0, bh1);
            mma_tf32(cm[i], al, bh0, bh1);
            mma_tf32(cm[i], ah, bl0, bl1);
        }
    }
#pragma unroll
    for (int i = 0; i < 2; i++) {
        int r0 = (mt2 + i) * 16 + g;
        *(float2*)&dst[r0 * HP + colm + 2 * t4] = make_float2(cm[i][0], cm[i][1]);
        *(float2*)&dst[(r0 + 8) * HP + colm + 2 * t4] = make_float2(cm[i][2], cm[i][3]);
    }
}

// one gate hop (8 k-tiles starting at kb) accumulating into c[3][4]
__device__ __forceinline__ void gate_hop_mma(float c[3][4], const float* __restrict__ sH,
                                             const unsigned* __restrict__ sWh,
                                             int kb, int r0, int t4, int g,
                                             const int epb[3], const int egl[3])
{
#pragma unroll 2
    for (int kt = 0; kt < 8; kt++) {
        int kg = kb + kt * 8;
        float a0f = sH[r0 * HP + kg + t4];
        float a1f = sH[(r0 + 8) * HP + kg + t4];
        float a2f = sH[r0 * HP + kg + t4 + 4];
        float a3f = sH[(r0 + 8) * HP + kg + t4 + 4];
        unsigned ah[4] = {f2tf(a0f), f2tf(a1f), f2tf(a2f), f2tf(a3f)};
        unsigned al[4] = {f2tf(a0f - __uint_as_float(ah[0])),
                          f2tf(a1f - __uint_as_float(ah[1])),
                          f2tf(a2f - __uint_as_float(ah[2])),
                          f2tf(a3f - __uint_as_float(ah[3]))};
#pragma unroll
        for (int nt = 0; nt < 3; nt++) {
            unsigned bh0 = sWh[(kg + t4) * WP + epb[nt] + g];
            unsigned bh1 = sWh[(kg + t4 + 4) * WP + epb[nt] + g];
            unsigned bl0 = __ldg(&g_Wl[(kg + t4) * 192 + egl[nt] + g]);
            unsigned bl1 = __ldg(&g_Wl[(kg + t4 + 4) * 192 + egl[nt] + g]);
            mma_tf32(c[nt], ah, bh0, bh1);
            mma_tf32(c[nt], al, bh0, bh1);
            mma_tf32(c[nt], ah, bl0, bl1);
        }
    }
}

__global__ void __launch_bounds__(512, 1) __cluster_dims__(2, 1, 1) phase2_kernel(
    const float* __restrict__ adj, const float* __restrict__ h0,
    const float* __restrict__ Wfh, const float* __restrict__ Wgh, const float* __restrict__ Wch,
    float* __restrict__ out)
{
    extern __shared__ char smc[];
    unsigned* sWh = (unsigned*)smc;              // 79872
    float* sH  = (float*)(smc + 79872);          // 50176
    float* sAN = (float*)(smc + 130048);         // 17408
    float* sG  = (float*)(smc + 147456);         // 26624

    const int tid = threadIdx.x;
    const int b = blockIdx.x >> 1;
    const unsigned rank = cluster_rank();
    const unsigned peer = rank ^ 1u;
    const int dbase = (int)rank * 32;

    for (int i = tid; i < 192 * 96; i += 512) {
        int k = i / 96, ep = i % 96;
        int gate = ep >> 5, dloc = ep & 31;
        int hop = k >> 6, dm = k & 63;
        const float* W = (gate == 0) ? Wfh : ((gate == 1) ? Wgh : Wch);
        sWh[k * WP + ep] = f2tf(W[hop * 4096 + dm * 64 + dbase + dloc]);
    }
    for (int i = tid; i < 4096; i += 512) {
        int n = i >> 6, d = i & 63;
        sH[n * HP + d] = h0[b * 4096 + i];
    }
    __syncthreads();
    CLUSTER_SYNC();
    CLUSTER_ARRIVE();

    const unsigned u_sH = smem_u32(sH);

    const int mn0 = (tid >> 4) * 2;
    const int mdl = (tid & 15) * 2;

    const int w = tid >> 5, lane = tid & 31;
    const int g = lane >> 2, t4 = lane & 3;
    const int mt = w & 3, ng = w >> 2;
    const int r0 = mt * 16 + g;
    const int colm = (w & 7) * 8;
    const int mt2 = (w >> 3) * 2;

    int epb[3], egl[3];
#pragma unroll
    for (int nt = 0; nt < 3; nt++) {
        epb[nt] = (ng * 3 + nt) * 8;
        int gate = epb[nt] >> 5;
        egl[nt] = gate * 64 + dbase + (epb[nt] & 31);
    }

    float2 pu[6];
    {
        const float* Ub = g_U + ((size_t)(b * NT)) * (NN * NE);
#pragma unroll
        for (int nt = 0; nt < 3; nt++) {
            pu[nt * 2]     = *(const float2*)&Ub[r0 * NE + egl[nt] + 2 * t4];
            pu[nt * 2 + 1] = *(const float2*)&Ub[(r0 + 8) * NE + egl[nt] + 2 * t4];
        }
    }

    for (int t = 0; t < NT; t++) {
        CLUSTER_WAIT();
        __syncthreads();

        float c[3][4];
#pragma unroll
        for (int nt = 0; nt < 3; nt++) {
            c[nt][0] = pu[nt * 2].x;     c[nt][1] = pu[nt * 2].y;
            c[nt][2] = pu[nt * 2 + 1].x; c[nt][3] = pu[nt * 2 + 1].y;
        }
        {
            int btn = b * NT + t + 1;
            if (btn > NB * NT - 1) btn = NB * NT - 1;
            const float* Ub = g_U + (size_t)btn * (NN * NE);
#pragma unroll
            for (int nt = 0; nt < 3; nt++) {
                pu[nt * 2]     = *(const float2*)&Ub[r0 * NE + egl[nt] + 2 * t4];
                pu[nt * 2 + 1] = *(const float2*)&Ub[(r0 + 8) * NE + egl[nt] + 2 * t4];
            }
        }
        if (rank == 0 && t > 0) {
            int d = tid >> 3, q = tid & 7;
            float s = 0.f;
#pragma unroll
            for (int nn = 0; nn < 8; nn++) s += sH[(q * 8 + nn) * HP + d];
            s += __shfl_xor_sync(0xFFFFFFFFu, s, 1);
            s += __shfl_xor_sync(0xFFFFFFFFu, s, 2);
            s += __shfl_xor_sync(0xFFFFFFFFu, s, 4);
            if (q == 0)
                g_pool[((size_t)(b * NT + t - 1)) * NH + d] = s * (1.0f / 64.0f);
        }
        {
            const float4* Ap4 = (const float4*)(adj + ((size_t)(b * NT + t)) * 4096);
            for (int i = tid; i < 1024; i += 512) {
                int n = i >> 4, q = i & 15;
                *(float4*)&sAN[n * TP + q * 4] = __ldg(&Ap4[i]);
            }
        }
        __syncthreads();   // sAN ready

        // segment A: mm1 (writes hop1 cols) || hop0 gates (reads hop0 cols)
        mm_mma2(sH + 64, sAN, sH, g, t4, colm, mt2);
        gate_hop_mma(c, sH, sWh, 0, r0, t4, g, epb, egl);
        __syncthreads();

        // segment B: mm2 (writes hop2 cols) || hop1 gates (reads hop1 cols)
        mm_mma2(sH + 128, sAN, sH + 64, g, t4, colm, mt2);
        gate_hop_mma(c, sH, sWh, 64, r0, t4, g, epb, egl);
        __syncthreads();

        // segment C: hop2 gates + store G
        gate_hop_mma(c, sH, sWh, 128, r0, t4, g, epb, egl);
#pragma unroll
        for (int nt = 0; nt < 3; nt++) {
            int col = epb[nt] + 2 * t4;
            *(float2*)&sG[r0 * GP + col] = make_float2(c[nt][0], c[nt][1]);
            *(float2*)&sG[(r0 + 8) * GP + col] = make_float2(c[nt][2], c[nt][3]);
        }
        __syncthreads();

        // nonlinearity -> h_new own d-cols; write local + push peer
#pragma unroll
        for (int i = 0; i < 2; i++) {
            int row = mn0 + i;
            float hv[2];
#pragma unroll
            for (int j = 0; j < 2; j++) {
                float fv = sG[row * GP + mdl + j];
                float gv = sG[row * GP + 32 + mdl + j];
                float cv = sG[row * GP + 64 + mdl + j];
                float f = sig_fast(fv);
                float tg = tanh_fast(gv);
                float tc = tanh_fast(cv);
                hv[j] = f * (tg - tc) + tc;
            }
            int off = row * HP + dbase + mdl;
            *(float2*)&sH[off] = make_float2(hv[0], hv[1]);
            st_peer_f2(u_sH + (unsigned)off * 4u, peer, hv[0], hv[1]);
        }
        CLUSTER_ARRIVE();
    }

    CLUSTER_WAIT();

    if (rank == 0) {
        {
            int d = tid >> 3, q = tid & 7;
            float s = 0.f;
#pragma unroll
            for (int nn = 0; nn < 8; nn++) s += sH[(q * 8 + nn) * HP + d];
            s += __shfl_xor_sync(0xFFFFFFFFu, s, 1);
            s += __shfl_xor_sync(0xFFFFFFFFu, s, 2);
            s += __shfl_xor_sync(0xFFFFFFFFu, s, 4);
            if (q == 0)
                g_pool[((size_t)(b * NT + NT - 1)) * NH + d] = s * (1.0f / 64.0f);
        }
        float* fh = out + (size_t)NB * NT * 6 + (size_t)b * (NN * NH);
        for (int i = tid; i < 4096; i += 512)
            fh[i] = sH[(i >> 6) * HP + (i & 63)];
    }
}

// ---------------------------------------------------------------------------
// Phase 3: decoder MLP per (b,t). grid 8192, block 128.
// ---------------------------------------------------------------------------
__global__ void __launch_bounds__(128, 8) phase3_kernel(
    const float* __restrict__ dW1, const float* __restrict__ db1,
    const float* __restrict__ dW2, const float* __restrict__ db2,
    const float* __restrict__ dW3, const float* __restrict__ db3,
    const float* __restrict__ osc, const float* __restrict__ obi,
    float* __restrict__ out)
{
    __shared__ float sp[64];
    __shared__ float z1[128];
    __shared__ float z2[64];
    const int bt = blockIdx.x;
    const int tid = threadIdx.x;

    if (tid < 64) sp[tid] = g_pool[(size_t)bt * NH + tid];
    __syncthreads();
    {
        float a = db1[tid];
#pragma unroll 4
        for (int d = 0; d < 64; d++) a += sp[d] * dW1[d * 128 + tid];
        z1[tid] = fmaxf(a, 0.f);
    }
    __syncthreads();
    if (tid < 64) {
        float a = db2[tid];
#pragma unroll 4
        for (int i = 0; i < 128; i++) a += z1[i] * dW2[i * 64 + tid];
        z2[tid] = fmaxf(a, 0.f);
    }
    __syncthreads();
    if (tid < 6) {
        float a = db3[tid];
#pragma unroll 4
        for (int j = 0; j < 64; j++) a += z2[j] * dW3[j * 6 + tid];
        out[(size_t)bt * 6 + tid] = a * osc[tid] + obi[tid];
    }
}

extern "C" void kernel_launch(void* const* d_in, const int* in_sizes, int n_in,
                              void* d_out, int out_size) {
    const float* frames = (const float*)d_in[0];
    const float* adj    = (const float*)d_in[1];
    const float* h0     = (const float*)d_in[2];
    const float* encW   = (const float*)d_in[3];
    const float* encB   = (const float*)d_in[4];
    const float* Wfh    = (const float*)d_in[5];
    const float* Wfu    = (const float*)d_in[6];
    const float* bf     = (const float*)d_in[7];
    const float* Wgh    = (const float*)d_in[8];
    const float* Wgu    = (const float*)d_in[9];
    const float* bg     = (const float*)d_in[10];
    const float* Wch    = (const float*)d_in[11];
    const float* Wcu    = (const float*)d_in[12];
    const float* bc     = (const float*)d_in[13];
    const float* dW1    = (const float*)d_in[14];
    const float* db1    = (const float*)d_in[15];
    const float* dW2    = (const float*)d_in[16];
    const float* db2    = (const float*)d_in[17];
    const float* dW3    = (const float*)d_in[18];
    const float* db3    = (const float*)d_in[19];
    const float* osc    = (const float*)d_in[20];
    const float* obi    = (const float*)d_in[21];
    float* out = (float*)d_out;

    const int smem1 = 17408 * 4;   // 69632 B -> 2 CTAs/SM
    const int smem2 = 174080;
    cudaFuncSetAttribute(phase1_kernel, cudaFuncAttributeMaxDynamicSharedMemorySize, smem1);
    cudaFuncSetAttribute(phase2_kernel, cudaFuncAttributeMaxDynamicSharedMemorySize, smem2);

    prep1_kernel<<<176, 256>>>(Wfu, Wgu, Wcu, encW);
    prep2_kernel<<<144, 256>>>(Wfh, Wgh, Wch);
    phase1_kernel<<<NB * NT, 256, smem1>>>(frames, adj, encB, bf, bg, bc);
    phase2_kernel<<<NB * 2, 512, smem2>>>(adj, h0, Wfh, Wgh, Wch, out);
    phase3_kernel<<<NB * NT, 128>>>(dW1, db1, dW2, db2, dW3, db3, osc, obi, out);
}